// round 3
// baseline (speedup 1.0000x reference)
#include <cuda_runtime.h>

#define NN 25000
#define EE 100000
#define FIN 16
#define NH 4
#define CC 280
#define EDIM 6
#define NCLS 6
#define HC 1120   // NH*CC

#define KF 112    // padded feature length (108 -> 112)
#define C2 288    // padded hidden (280 -> 288)
#define H1DIM 64
#define H2DIM 16

// ---------------- scratch (device globals; no allocations allowed) ----------------
__device__ __align__(16) float g_M[NH * 16 * 16];      // per-head bilinear Wq Wk^T (1024)
__device__ __align__(16) float g_G[NH * EDIM * 16];    // per-head Wq We_d^T (384)
__device__ __align__(16) float g_g0[NH * EDIM];
__device__ __align__(16) float g_u[NH * 16];
__device__ __align__(16) float g_w[NH * 16];
__device__ __align__(16) float g_c0[NH];

__device__ __align__(16) float g_p[NN * 64];           // x_i @ M_h        [N][H][16]
__device__ __align__(16) float g_xg[NN * 24];          // x_i . G[h,d]+g0  [N][H][6]
__device__ __align__(16) float g_sd[NN * 4];           // dst-side scalar
__device__ __align__(16) float g_ss[NN * 4];           // src-side scalar

__device__ __align__(16) float g_T[NN * 64];           // sum ex * x[src]
__device__ __align__(16) float g_S[NN * 24];           // sum ex * ea
__device__ __align__(16) float g_A[NN * 4];            // sum ex

__device__ __align__(16) float g_F[NN * KF];           // fused node features [N][112]
__device__ __align__(16) float g_H[NN * C2];           // hidden 280(pad 288)
__device__ __align__(16) float g_W108[KF * C2];        // stacked weight [112][288]
__device__ __align__(16) float g_W1p[C2 * H1DIM];      // padded W1 [288][64]

// ---------------- K0a: tiny weight contractions ----------------
// index budget: M 1024 | G 384 | u 64 | w 64 | c0 4 | g0 24  => 1564
__global__ void k0a(const float* __restrict__ Wq, const float* __restrict__ bq,
                    const float* __restrict__ Wk, const float* __restrict__ bk,
                    const float* __restrict__ We) {
    int idx = blockIdx.x * blockDim.x + threadIdx.x;
    if (idx >= 1564) return;
    if (idx < 1024) {
        int h = idx >> 8, a = (idx >> 4) & 15, b = idx & 15;
        const float* qa = Wq + a * HC + h * CC;
        const float* kb = Wk + b * HC + h * CC;
        float s = 0.f;
        for (int c = 0; c < CC; c++) s += qa[c] * kb[c];
        g_M[idx] = s;
    } else if (idx < 1408) {
        int t = idx - 1024;
        int h = t / 96, r = t % 96, dd = r / 16, a = r % 16;
        const float* qa = Wq + a * HC + h * CC;
        const float* ed = We + dd * HC + h * CC;
        float s = 0.f;
        for (int c = 0; c < CC; c++) s += qa[c] * ed[c];
        g_G[(h * EDIM + dd) * 16 + a] = s;
    } else if (idx < 1472) {
        int t = idx - 1408;
        int h = t >> 4, a = t & 15;
        const float* qa = Wq + a * HC + h * CC;
        const float* bb = bk + h * CC;
        float s = 0.f;
        for (int c = 0; c < CC; c++) s += qa[c] * bb[c];
        g_u[h * 16 + a] = s;
    } else if (idx < 1536) {
        int t = idx - 1472;
        int h = t >> 4, a = t & 15;
        const float* ka = Wk + a * HC + h * CC;
        const float* bb = bq + h * CC;
        float s = 0.f;
        for (int c = 0; c < CC; c++) s += ka[c] * bb[c];
        g_w[h * 16 + a] = s;
    } else if (idx < 1540) {
        int h = idx - 1536;
        const float* b1p = bq + h * CC;
        const float* b2p = bk + h * CC;
        float s = 0.f;
        for (int c = 0; c < CC; c++) s += b1p[c] * b2p[c];
        g_c0[h] = s;
    } else {
        int t = idx - 1540;
        int h = t / 6, dd = t % 6;
        const float* bb = bq + h * CC;
        const float* ed = We + dd * HC + h * CC;
        float s = 0.f;
        for (int c = 0; c < CC; c++) s += bb[c] * ed[c];
        g_g0[h * 6 + dd] = s;
    }
}

// ---------------- K0b: build stacked output weight [112][288] ----------------
__global__ void k0b(const float* __restrict__ Wv, const float* __restrict__ bv,
                    const float* __restrict__ We, const float* __restrict__ Wskip) {
    int idx = blockIdx.x * blockDim.x + threadIdx.x;
    if (idx >= KF * C2) return;
    int j = idx / C2, c = idx % C2;
    float v = 0.f;
    if (c < CC) {
        if (j < 64) {
            int h = j >> 4, a = j & 15;
            v = 0.25f * Wv[a * HC + h * CC + c];
        } else if (j < 88) {
            int t = j - 64, h = t / 6, dd = t % 6;
            v = 0.25f * We[dd * HC + h * CC + c];
        } else if (j < 104) {
            int a = j - 88;
            v = Wskip[a * CC + c];
        } else if (j < 108) {
            int h = j - 104;
            v = 0.25f * bv[h * CC + c];
        }
    }
    g_W108[idx] = v;
}

// ---------------- K0c: pad W1 to [288][64] ----------------
__global__ void k0c(const float* __restrict__ W1) {
    int idx = blockIdx.x * blockDim.x + threadIdx.x;
    if (idx >= C2 * H1DIM) return;
    int k = idx / H1DIM;
    g_W1p[idx] = (k < CC) ? W1[idx] : 0.f;
}

// ---------------- K1: per-node precompute (p, xg, scalars) + zero accumulators ----------------
__global__ void k1(const float* __restrict__ x) {
    __shared__ float sM[NH * 16 * 16];
    __shared__ float sG[NH * EDIM * 16];
    __shared__ float sU[NH * 16];
    __shared__ float sW[NH * 16];
    __shared__ float sC0[NH];
    __shared__ float sG0[NH * EDIM];
    for (int t = threadIdx.x; t < NH * 256; t += blockDim.x) sM[t] = g_M[t];
    for (int t = threadIdx.x; t < NH * EDIM * 16; t += blockDim.x) sG[t] = g_G[t];
    for (int t = threadIdx.x; t < NH * 16; t += blockDim.x) { sU[t] = g_u[t]; sW[t] = g_w[t]; }
    for (int t = threadIdx.x; t < NH; t += blockDim.x) sC0[t] = g_c0[t];
    for (int t = threadIdx.x; t < NH * EDIM; t += blockDim.x) sG0[t] = g_g0[t];
    __syncthreads();

    int i = blockIdx.x * blockDim.x + threadIdx.x;
    if (i >= NN) return;
    float xv[16];
    const float4* xr = (const float4*)(x + (size_t)i * 16);
#pragma unroll
    for (int t = 0; t < 4; t++) {
        float4 f = xr[t];
        xv[4 * t + 0] = f.x; xv[4 * t + 1] = f.y; xv[4 * t + 2] = f.z; xv[4 * t + 3] = f.w;
    }
#pragma unroll
    for (int h = 0; h < NH; h++) {
#pragma unroll
        for (int b = 0; b < 16; b++) {
            float s = 0.f;
#pragma unroll
            for (int a = 0; a < 16; a++) s += xv[a] * sM[(h * 16 + a) * 16 + b];
            g_p[i * 64 + h * 16 + b] = s;
            g_T[i * 64 + h * 16 + b] = 0.f;
        }
#pragma unroll
        for (int dd = 0; dd < EDIM; dd++) {
            float s = sG0[h * EDIM + dd];
#pragma unroll
            for (int a = 0; a < 16; a++) s += xv[a] * sG[(h * EDIM + dd) * 16 + a];
            g_xg[i * 24 + h * 6 + dd] = s;
            g_S[i * 24 + h * 6 + dd] = 0.f;
        }
        float su = sC0[h], sw = 0.f;
#pragma unroll
        for (int a = 0; a < 16; a++) {
            su += xv[a] * sU[h * 16 + a];
            sw += xv[a] * sW[h * 16 + a];
        }
        g_sd[i * 4 + h] = su;
        g_ss[i * 4 + h] = sw;
        g_A[i * 4 + h] = 0.f;
    }
}

// ---------------- K2: edge pass (logits + exp + atomic scatter) ----------------
// edge_index is int32 on disk (JAX x64 disabled downcasts int64 -> int32)
__global__ void k2(const int* __restrict__ ei, const float* __restrict__ x,
                   const float* __restrict__ ea) {
    int e = blockIdx.x * blockDim.x + threadIdx.x;
    if (e >= EE) return;
    int s = ei[e];
    int d = ei[EE + e];

    float xs[16];
    const float4* xr = (const float4*)(x + (size_t)s * 16);
#pragma unroll
    for (int t = 0; t < 4; t++) {
        float4 f = xr[t];
        xs[4 * t + 0] = f.x; xs[4 * t + 1] = f.y; xs[4 * t + 2] = f.z; xs[4 * t + 3] = f.w;
    }
    float eav[6];
#pragma unroll
    for (int dd = 0; dd < 6; dd++) eav[dd] = ea[(size_t)e * 6 + dd];

    float4 sd4 = *(const float4*)(g_sd + d * 4);
    float4 ss4 = *(const float4*)(g_ss + s * 4);
    float sdv[4] = {sd4.x, sd4.y, sd4.z, sd4.w};
    float ssv[4] = {ss4.x, ss4.y, ss4.z, ss4.w};

#pragma unroll
    for (int h = 0; h < NH; h++) {
        float al = sdv[h] + ssv[h];
        const float4* pd = (const float4*)(g_p + d * 64 + h * 16);
#pragma unroll
        for (int t = 0; t < 4; t++) {
            float4 f = pd[t];
            al += f.x * xs[4 * t + 0] + f.y * xs[4 * t + 1] + f.z * xs[4 * t + 2] + f.w * xs[4 * t + 3];
        }
        const float* xgd = g_xg + d * 24 + h * 6;
#pragma unroll
        for (int dd = 0; dd < 6; dd++) al += eav[dd] * xgd[dd];
        al *= 0.05976143046671968f;  // 1/sqrt(280)
        float ex = __expf(al);

        atomicAdd(&g_A[d * 4 + h], ex);
        float* Sd = g_S + d * 24 + h * 6;
#pragma unroll
        for (int dd = 0; dd < 6; dd++) atomicAdd(Sd + dd, ex * eav[dd]);
        float* Td = g_T + d * 64 + h * 16;
#pragma unroll
        for (int k = 0; k < 16; k++) atomicAdd(Td + k, ex * xs[k]);
    }
}

// ---------------- K3a: normalize + assemble fused features F[N][112] ----------------
__global__ void k3a(const float* __restrict__ x) {
    int idx = blockIdx.x * blockDim.x + threadIdx.x;
    if (idx >= NN * KF) return;
    int i = idx / KF;
    int j = idx - i * KF;
    float v;
    if (j < 64) {
        int h = j >> 4;
        v = g_T[i * 64 + j] / (g_A[i * 4 + h] + 1e-16f);
    } else if (j < 88) {
        int t = j - 64, h = t / 6;
        v = g_S[i * 24 + t] / (g_A[i * 4 + h] + 1e-16f);
    } else if (j < 104) {
        v = x[i * 16 + (j - 88)];
    } else if (j < 108) {
        float a = g_A[i * 4 + (j - 104)];
        v = a / (a + 1e-16f);
    } else {
        v = 0.f;
    }
    g_F[idx] = v;
}

// ---------------- K4: GEMM1  H[N][288] = F[N][112] @ W108 + bskip ----------------
__global__ __launch_bounds__(256) void k4(const float* __restrict__ bskip) {
    __shared__ float Fs[28][129];  // [k][row], 128 rows padded to 129
    __shared__ float Ws[28][96];
    int tid = threadIdx.x;
    int tx = tid & 15, ty = tid >> 4;
    int nodeBase = blockIdx.x * 128;
    int colBase = blockIdx.y * 96;
    float acc[8][6];
#pragma unroll
    for (int i = 0; i < 8; i++)
#pragma unroll
        for (int j = 0; j < 6; j++) acc[i][j] = 0.f;

    for (int kc = 0; kc < 4; kc++) {
        int k0 = kc * 28;
        for (int idx = tid; idx < 128 * 28; idx += 256) {
            int r = idx / 28, k = idx % 28;
            int node = nodeBase + r;
            Fs[k][r] = (node < NN) ? g_F[node * KF + k0 + k] : 0.f;
        }
        for (int idx = tid; idx < 28 * 96; idx += 256) {
            int k = idx / 96, c = idx % 96;
            Ws[k][c] = g_W108[(k0 + k) * C2 + colBase + c];
        }
        __syncthreads();
#pragma unroll
        for (int k = 0; k < 28; k++) {
            float fv[8], wv[6];
#pragma unroll
            for (int i = 0; i < 8; i++) fv[i] = Fs[k][ty * 8 + i];
#pragma unroll
            for (int j = 0; j < 6; j++) wv[j] = Ws[k][tx * 6 + j];
#pragma unroll
            for (int i = 0; i < 8; i++)
#pragma unroll
                for (int j = 0; j < 6; j++) acc[i][j] += fv[i] * wv[j];
        }
        __syncthreads();
    }
#pragma unroll
    for (int i = 0; i < 8; i++) {
        int node = nodeBase + ty * 8 + i;
        if (node < NN) {
#pragma unroll
            for (int j = 0; j < 6; j++) {
                int c = colBase + tx * 6 + j;
                float b = (c < CC) ? __ldg(&bskip[c]) : 0.f;
                g_H[node * C2 + c] = acc[i][j] + b;
            }
        }
    }
}

// ---------------- K5: GEMM2 (H @ W1p, relu) fused with MLP tail + softmax ----------------
__global__ __launch_bounds__(256) void k5(const float* __restrict__ b1,
                                          const float* __restrict__ W2,
                                          const float* __restrict__ b2,
                                          const float* __restrict__ W3,
                                          const float* __restrict__ b3,
                                          float* __restrict__ out) {
    __shared__ float Hs[32][65];
    __shared__ float Ws1[32][64];
    __shared__ float Hs1[64][68];
    __shared__ float W2s[64 * 16];
    __shared__ float b2s[16];
    __shared__ float W3s[16 * 6];
    __shared__ float b3s[6];

    int tid = threadIdx.x;
    int tx = tid & 15, ty = tid >> 4;
    int nodeBase = blockIdx.x * 64;

    for (int t = tid; t < 64 * 16; t += 256) W2s[t] = W2[t];
    if (tid < 16) b2s[tid] = b2[tid];
    if (tid < 96) W3s[tid] = W3[tid];
    if (tid < 6) b3s[tid] = b3[tid];

    float acc[4][4];
#pragma unroll
    for (int i = 0; i < 4; i++)
#pragma unroll
        for (int j = 0; j < 4; j++) acc[i][j] = 0.f;

    for (int kc = 0; kc < 9; kc++) {
        int k0 = kc * 32;
        for (int idx = tid; idx < 64 * 32; idx += 256) {
            int r = idx / 32, k = idx % 32;
            int node = nodeBase + r;
            Hs[k][r] = (node < NN) ? g_H[node * C2 + k0 + k] : 0.f;
        }
        for (int idx = tid; idx < 32 * 64; idx += 256) {
            int k = idx / 64, c = idx % 64;
            Ws1[k][c] = g_W1p[(k0 + k) * 64 + c];
        }
        __syncthreads();
#pragma unroll
        for (int k = 0; k < 32; k++) {
            float fv[4], wv[4];
#pragma unroll
            for (int i = 0; i < 4; i++) fv[i] = Hs[k][ty * 4 + i];
#pragma unroll
            for (int j = 0; j < 4; j++) wv[j] = Ws1[k][tx * 4 + j];
#pragma unroll
            for (int i = 0; i < 4; i++)
#pragma unroll
                for (int j = 0; j < 4; j++) acc[i][j] += fv[i] * wv[j];
        }
        __syncthreads();
    }

    // relu + stash H1 tile
#pragma unroll
    for (int i = 0; i < 4; i++)
#pragma unroll
        for (int j = 0; j < 4; j++)
            Hs1[ty * 4 + i][tx * 4 + j] = fmaxf(acc[i][j] + b1[tx * 4 + j], 0.f);
    __syncthreads();

    // stage 2: 4 lanes per node
    int n = tid >> 2, q = tid & 3;
    int node = nodeBase + n;
    float h2[4];
#pragma unroll
    for (int mm = 0; mm < 4; mm++) h2[mm] = b2s[q * 4 + mm];
    for (int k = 0; k < 64; k++) {
        float hv = Hs1[n][k];
#pragma unroll
        for (int mm = 0; mm < 4; mm++) h2[mm] += hv * W2s[k * 16 + q * 4 + mm];
    }
#pragma unroll
    for (int mm = 0; mm < 4; mm++) h2[mm] = fmaxf(h2[mm], 0.f);

    float lg[6];
#pragma unroll
    for (int o = 0; o < 6; o++) {
        float pz = 0.f;
#pragma unroll
        for (int mm = 0; mm < 4; mm++) pz += h2[mm] * W3s[(q * 4 + mm) * 6 + o];
        lg[o] = pz;
    }
#pragma unroll
    for (int o = 0; o < 6; o++) {
        lg[o] += __shfl_xor_sync(0xffffffffu, lg[o], 1);
        lg[o] += __shfl_xor_sync(0xffffffffu, lg[o], 2);
        lg[o] += b3s[o];
    }
    float mx = lg[0];
#pragma unroll
    for (int o = 1; o < 6; o++) mx = fmaxf(mx, lg[o]);
    float ev[6], sum = 0.f;
#pragma unroll
    for (int o = 0; o < 6; o++) { ev[o] = expf(lg[o] - mx); sum += ev[o]; }
    float inv = 1.f / sum;
    if (q == 0 && node < NN) {
#pragma unroll
        for (int o = 0; o < 6; o++) out[node * 6 + o] = ev[o] * inv;
    }
}

// ---------------- launch ----------------
extern "C" void kernel_launch(void* const* d_in, const int* in_sizes, int n_in,
                              void* d_out, int out_size) {
    const float* x      = (const float*)d_in[0];
    const int* ei       = (const int*)d_in[1];   // int32 (JAX downcasts int64)
    const float* ea     = (const float*)d_in[2];
    const float* Wq     = (const float*)d_in[3];
    const float* bq     = (const float*)d_in[4];
    const float* Wk     = (const float*)d_in[5];
    const float* bk     = (const float*)d_in[6];
    const float* Wv     = (const float*)d_in[7];
    const float* bv     = (const float*)d_in[8];
    const float* We     = (const float*)d_in[9];
    const float* Wskip  = (const float*)d_in[10];
    const float* bskip  = (const float*)d_in[11];
    const float* W1     = (const float*)d_in[12];
    const float* b1     = (const float*)d_in[13];
    const float* W2     = (const float*)d_in[14];
    const float* b2     = (const float*)d_in[15];
    const float* W3     = (const float*)d_in[16];
    const float* b3     = (const float*)d_in[17];
    float* out = (float*)d_out;

    k0a<<<(1564 + 127) / 128, 128>>>(Wq, bq, Wk, bk, We);
    k0b<<<(KF * C2 + 255) / 256, 256>>>(Wv, bv, We, Wskip);
    k0c<<<(C2 * H1DIM + 255) / 256, 256>>>(W1);
    k1<<<(NN + 127) / 128, 128>>>(x);
    k2<<<(EE + 255) / 256, 256>>>(ei, x, ea);
    k3a<<<(NN * KF + 255) / 256, 256>>>(x);
    dim3 g4((NN + 127) / 128, 3);
    k4<<<g4, 256>>>(bskip);
    k5<<<(NN + 63) / 64, 256>>>(b1, W2, b2, W3, b3, out);
}

// round 4
// speedup vs baseline: 2.3556x; 2.3556x over previous
#include <cuda_runtime.h>

#define NN 25000
#define EE 100000
#define NH 4
#define CC 280
#define HC 1120

// ---------------- scratch ----------------
__device__ __align__(16) float g_M[NH * 256];
__device__ __align__(16) float g_G[NH * 6 * 16];
__device__ __align__(16) float g_g0[NH * 6];
__device__ __align__(16) float g_u[NH * 16];
__device__ __align__(16) float g_w[NH * 16];
__device__ __align__(16) float g_c0[NH];

__device__ __align__(16) float g_p[NN * 64];     // x_i @ M_h  [N][H][16]
__device__ __align__(16) float g_xgp[NN * 32];   // [N][H][8] (6 used)
__device__ __align__(16) float g_sd[NN * 4];
__device__ __align__(16) float g_ss[NN * 4];

__device__ __align__(16) float g_T[NN * 64];     // sum ex*x[src]  [N][H][16]
__device__ __align__(16) float g_Sp[NN * 32];    // sum ex*ea      [N][H][8] (6 used)
__device__ __align__(16) float g_A[NN * 4];      // sum ex

__device__ __align__(16) float g_Wc[112 * 64];   // combined (W108 @ W1)
__device__ __align__(16) float g_bc[64];         // b1 + bskip @ W1

__device__ __forceinline__ float wsum(float s) {
    s += __shfl_xor_sync(0xffffffffu, s, 16);
    s += __shfl_xor_sync(0xffffffffu, s, 8);
    s += __shfl_xor_sync(0xffffffffu, s, 4);
    s += __shfl_xor_sync(0xffffffffu, s, 2);
    s += __shfl_xor_sync(0xffffffffu, s, 1);
    return s;
}

__device__ __forceinline__ void red4(float* p, float a, float b, float c, float d) {
    asm volatile("red.global.add.v4.f32 [%0], {%1,%2,%3,%4};"
                 :: "l"(__cvta_generic_to_global(p)), "f"(a), "f"(b), "f"(c), "f"(d) : "memory");
}
__device__ __forceinline__ void red2(float* p, float a, float b) {
    asm volatile("red.global.add.v2.f32 [%0], {%1,%2};"
                 :: "l"(__cvta_generic_to_global(p)), "f"(a), "f"(b) : "memory");
}

// ---------------- K0a: tiny weight contractions (warp per output) ----------------
// M 1024 | G 384 | u 64 | w 64 | c0 4 | g0 24 => 1564 warps
__global__ void k0a(const float* __restrict__ Wq, const float* __restrict__ bq,
                    const float* __restrict__ Wk, const float* __restrict__ bk,
                    const float* __restrict__ We) {
    int g = blockIdx.x * 8 + (threadIdx.x >> 5);
    int lane = threadIdx.x & 31;
    if (g >= 1564) return;
    const float *pa, *pb;
    float* op;
    if (g < 1024) {
        int h = g >> 8, a = (g >> 4) & 15, b = g & 15;
        pa = Wq + a * HC + h * CC; pb = Wk + b * HC + h * CC; op = &g_M[g];
    } else if (g < 1408) {
        int t = g - 1024, h = t / 96, r = t % 96, dd = r >> 4, a = r & 15;
        pa = Wq + a * HC + h * CC; pb = We + dd * HC + h * CC; op = &g_G[(h * 6 + dd) * 16 + a];
    } else if (g < 1472) {
        int t = g - 1408, h = t >> 4, a = t & 15;
        pa = Wq + a * HC + h * CC; pb = bk + h * CC; op = &g_u[t];
    } else if (g < 1536) {
        int t = g - 1472, h = t >> 4, a = t & 15;
        pa = Wk + a * HC + h * CC; pb = bq + h * CC; op = &g_w[t];
    } else if (g < 1540) {
        int h = g - 1536;
        pa = bq + h * CC; pb = bk + h * CC; op = &g_c0[h];
    } else {
        int t = g - 1540, h = t / 6, dd = t - h * 6;
        pa = bq + h * CC; pb = We + dd * HC + h * CC; op = &g_g0[t];
    }
    float s = 0.f;
    for (int c = lane; c < CC; c += 32) s += pa[c] * pb[c];
    s = wsum(s);
    if (lane == 0) *op = s;
}

// ---------------- K0d: combined MLP front weight Wc[112][64], bc[64] ----------------
__global__ void k0d(const float* __restrict__ Wv, const float* __restrict__ bv,
                    const float* __restrict__ We, const float* __restrict__ Wskip,
                    const float* __restrict__ W1, const float* __restrict__ b1,
                    const float* __restrict__ bskip) {
    int g = blockIdx.x * 8 + (threadIdx.x >> 5);
    int lane = threadIdx.x & 31;
    if (g >= 7232) return;
    if (g < 7168) {
        int j = g >> 6, c = g & 63;
        float s = 0.f;
        if (j < 108) {
            const float* src;
            float sc = 0.25f;
            if (j < 64)      { int h = j >> 4, a = j & 15; src = Wv + a * HC + h * CC; }
            else if (j < 88) { int t = j - 64, h = t / 6, dd = t - h * 6; src = We + dd * HC + h * CC; }
            else if (j < 104){ src = Wskip + (j - 88) * CC; sc = 1.f; }
            else             { int h = j - 104; src = bv + h * CC; }
            for (int k = lane; k < CC; k += 32) s += src[k] * W1[k * 64 + c];
            s *= sc;
        }
        s = wsum(s);
        if (lane == 0) g_Wc[j * 64 + c] = s;
    } else {
        int c = g - 7168;
        float s = 0.f;
        for (int k = lane; k < CC; k += 32) s += bskip[k] * W1[k * 64 + c];
        s = wsum(s);
        if (lane == 0) g_bc[c] = s + b1[c];
    }
}

// ---------------- K1: per-(node,head) precompute + zero accumulators ----------------
__global__ __launch_bounds__(256) void k1(const float* __restrict__ x) {
    __shared__ float sM[NH * 256];
    __shared__ float sG[NH * 96];
    __shared__ float sU[NH * 16];
    __shared__ float sW[NH * 16];
    __shared__ float sC0[NH];
    __shared__ float sG0[NH * 6];
    for (int t = threadIdx.x; t < NH * 256; t += 256) sM[t] = g_M[t];
    if (threadIdx.x < NH * 96) sG[threadIdx.x] = g_G[threadIdx.x];
    if (threadIdx.x < NH * 16) { sU[threadIdx.x] = g_u[threadIdx.x]; sW[threadIdx.x] = g_w[threadIdx.x]; }
    if (threadIdx.x < NH) sC0[threadIdx.x] = g_c0[threadIdx.x];
    if (threadIdx.x < NH * 6) sG0[threadIdx.x] = g_g0[threadIdx.x];
    __syncthreads();

    int gid = blockIdx.x * 256 + threadIdx.x;
    int i = gid >> 2, h = gid & 3;
    if (i >= NN) return;
    float xv[16];
    const float4* xr = (const float4*)(x + (size_t)i * 16);
#pragma unroll
    for (int t = 0; t < 4; t++) {
        float4 f = xr[t];
        xv[4 * t + 0] = f.x; xv[4 * t + 1] = f.y; xv[4 * t + 2] = f.z; xv[4 * t + 3] = f.w;
    }
    const float4 z4 = make_float4(0.f, 0.f, 0.f, 0.f);
    float4* po = (float4*)(g_p + i * 64 + h * 16);
    float4* to = (float4*)(g_T + i * 64 + h * 16);
#pragma unroll
    for (int t = 0; t < 4; t++) {
        float pv[4];
#pragma unroll
        for (int j = 0; j < 4; j++) {
            int b = t * 4 + j;
            float s = 0.f;
#pragma unroll
            for (int a = 0; a < 16; a++) s += xv[a] * sM[(h * 16 + a) * 16 + b];
            pv[j] = s;
        }
        po[t] = make_float4(pv[0], pv[1], pv[2], pv[3]);
        to[t] = z4;
    }
    float xg[6];
#pragma unroll
    for (int dd = 0; dd < 6; dd++) {
        float s = sG0[h * 6 + dd];
#pragma unroll
        for (int a = 0; a < 16; a++) s += xv[a] * sG[(h * 6 + dd) * 16 + a];
        xg[dd] = s;
    }
    float4* xo = (float4*)(g_xgp + i * 32 + h * 8);
    xo[0] = make_float4(xg[0], xg[1], xg[2], xg[3]);
    *(float2*)(g_xgp + i * 32 + h * 8 + 4) = make_float2(xg[4], xg[5]);
    float4* so = (float4*)(g_Sp + i * 32 + h * 8);
    so[0] = z4; so[1] = z4;

    float su = sC0[h], sw = 0.f;
#pragma unroll
    for (int a = 0; a < 16; a++) {
        su += xv[a] * sU[h * 16 + a];
        sw += xv[a] * sW[h * 16 + a];
    }
    g_sd[i * 4 + h] = su;
    g_ss[i * 4 + h] = sw;
    g_A[i * 4 + h] = 0.f;
}

// ---------------- K2: edge pass, vectorized reds ----------------
__global__ __launch_bounds__(256) void k2(const int* __restrict__ ei,
                                          const float* __restrict__ x,
                                          const float* __restrict__ ea) {
    int e = blockIdx.x * 256 + threadIdx.x;
    if (e >= EE) return;
    int s = ei[e];
    int d = ei[EE + e];

    float xs[16];
    const float4* xr = (const float4*)(x + (size_t)s * 16);
#pragma unroll
    for (int t = 0; t < 4; t++) {
        float4 f = xr[t];
        xs[4 * t + 0] = f.x; xs[4 * t + 1] = f.y; xs[4 * t + 2] = f.z; xs[4 * t + 3] = f.w;
    }
    float eav[6];
    const float2* er = (const float2*)(ea + (size_t)e * 6);
#pragma unroll
    for (int t = 0; t < 3; t++) {
        float2 f = er[t];
        eav[2 * t] = f.x; eav[2 * t + 1] = f.y;
    }
    float4 sd4 = *(const float4*)(g_sd + d * 4);
    float4 ss4 = *(const float4*)(g_ss + s * 4);
    float sdv[4] = {sd4.x, sd4.y, sd4.z, sd4.w};
    float ssv[4] = {ss4.x, ss4.y, ss4.z, ss4.w};

    float exv[4];
#pragma unroll
    for (int h = 0; h < 4; h++) {
        float al = sdv[h] + ssv[h];
        const float4* pd = (const float4*)(g_p + d * 64 + h * 16);
#pragma unroll
        for (int t = 0; t < 4; t++) {
            float4 f = pd[t];
            al += f.x * xs[4 * t + 0] + f.y * xs[4 * t + 1] + f.z * xs[4 * t + 2] + f.w * xs[4 * t + 3];
        }
        float4 xga = *(const float4*)(g_xgp + d * 32 + h * 8);
        float2 xgb = *(const float2*)(g_xgp + d * 32 + h * 8 + 4);
        al += eav[0] * xga.x + eav[1] * xga.y + eav[2] * xga.z + eav[3] * xga.w
            + eav[4] * xgb.x + eav[5] * xgb.y;
        al *= 0.05976143046671968f;  // 1/sqrt(280)
        float ex = __expf(al);
        exv[h] = ex;

        float* Sd = g_Sp + d * 32 + h * 8;
        red4(Sd, ex * eav[0], ex * eav[1], ex * eav[2], ex * eav[3]);
        red2(Sd + 4, ex * eav[4], ex * eav[5]);
        float* Td = g_T + d * 64 + h * 16;
#pragma unroll
        for (int t = 0; t < 4; t++)
            red4(Td + 4 * t, ex * xs[4 * t], ex * xs[4 * t + 1], ex * xs[4 * t + 2], ex * xs[4 * t + 3]);
    }
    red4(g_A + d * 4, exv[0], exv[1], exv[2], exv[3]);
}

// ---------------- K6: fused normalize + F@Wc + relu + W2 + relu + W3 + softmax ----------------
#define K6DYN (7168 * 4 + 112 * 65 * 4)
__global__ __launch_bounds__(256) void k6(const float* __restrict__ x,
                                          const float* __restrict__ W2,
                                          const float* __restrict__ b2,
                                          const float* __restrict__ W3,
                                          const float* __restrict__ b3,
                                          float* __restrict__ out) {
    extern __shared__ float dyn[];
    float* Wcs = dyn;          // [112][64]
    float* Fs = dyn + 7168;    // [112][65]
    float* Hs1 = dyn;          // alias of Wcs, [64][68], used after stage 1
    __shared__ float invAs[256], als[256];
    __shared__ float W2s[1024], b2s[16], W3s[96], b3s[6], bcs[64];

    int tid = threadIdx.x;
    int nodeBase = blockIdx.x * 64;

    for (int t = tid; t < 7168; t += 256) Wcs[t] = g_Wc[t];
    for (int t = tid; t < 1024; t += 256) W2s[t] = W2[t];
    if (tid < 16) b2s[tid] = b2[tid];
    if (tid < 96) W3s[tid] = W3[tid];
    if (tid < 6) b3s[tid] = b3[tid];
    if (tid < 64) bcs[tid] = g_bc[tid];
    {
        int n = tid >> 2;
        int node = nodeBase + n;
        float a = (node < NN) ? g_A[node * 4 + (tid & 3)] : 0.f;
        float inv = 1.f / (a + 1e-16f);
        invAs[tid] = inv;
        als[tid] = a * inv;
    }
    __syncthreads();

    // fill Fs[k][n] (k-pitch 65)
    int wq = tid >> 5, lane = tid & 31;
#pragma unroll
    for (int r = 0; r < 8; r++) {
        int n = wq * 8 + r;
        int node = nodeBase + n;
        bool ok = node < NN;
#pragma unroll
        for (int t = 0; t < 2; t++) {
            int k = lane + t * 32;
            Fs[k * 65 + n] = ok ? g_T[node * 64 + k] * invAs[n * 4 + (k >> 4)] : 0.f;
        }
        if (lane < 24) {
            int h = lane / 6, dd = lane - h * 6;
            Fs[(64 + lane) * 65 + n] = ok ? g_Sp[node * 32 + h * 8 + dd] * invAs[n * 4 + h] : 0.f;
        }
        if (lane < 16) Fs[(88 + lane) * 65 + n] = ok ? x[(size_t)node * 16 + lane] : 0.f;
        if (lane < 4) {
            Fs[(104 + lane) * 65 + n] = als[n * 4 + lane];
            Fs[(108 + lane) * 65 + n] = 0.f;
        }
    }
    __syncthreads();

    // stage 1: [64 nodes] x [64 cols], K=112
    int tx = tid & 15, ty = tid >> 4;
    float acc[4][4];
#pragma unroll
    for (int i = 0; i < 4; i++)
#pragma unroll
        for (int j = 0; j < 4; j++) acc[i][j] = 0.f;
    for (int k = 0; k < 112; k++) {
        float fv[4], wv[4];
#pragma unroll
        for (int i = 0; i < 4; i++) fv[i] = Fs[k * 65 + ty * 4 + i];
#pragma unroll
        for (int j = 0; j < 4; j++) wv[j] = Wcs[k * 64 + tx * 4 + j];
#pragma unroll
        for (int i = 0; i < 4; i++)
#pragma unroll
            for (int j = 0; j < 4; j++) acc[i][j] += fv[i] * wv[j];
    }
    __syncthreads();  // done reading Wcs; safe to alias as Hs1
#pragma unroll
    for (int i = 0; i < 4; i++)
#pragma unroll
        for (int j = 0; j < 4; j++)
            Hs1[(ty * 4 + i) * 68 + tx * 4 + j] = fmaxf(acc[i][j] + bcs[tx * 4 + j], 0.f);
    __syncthreads();

    // stage 2+3: 4 lanes per node
    int n = tid >> 2, q = tid & 3;
    int node = nodeBase + n;
    float h2[4];
#pragma unroll
    for (int mm = 0; mm < 4; mm++) h2[mm] = b2s[q * 4 + mm];
    for (int k = 0; k < 64; k++) {
        float hv = Hs1[n * 68 + k];
#pragma unroll
        for (int mm = 0; mm < 4; mm++) h2[mm] += hv * W2s[k * 16 + q * 4 + mm];
    }
#pragma unroll
    for (int mm = 0; mm < 4; mm++) h2[mm] = fmaxf(h2[mm], 0.f);

    float lg[6];
#pragma unroll
    for (int o = 0; o < 6; o++) {
        float pz = 0.f;
#pragma unroll
        for (int mm = 0; mm < 4; mm++) pz += h2[mm] * W3s[(q * 4 + mm) * 6 + o];
        lg[o] = pz;
    }
#pragma unroll
    for (int o = 0; o < 6; o++) {
        lg[o] += __shfl_xor_sync(0xffffffffu, lg[o], 1);
        lg[o] += __shfl_xor_sync(0xffffffffu, lg[o], 2);
        lg[o] += b3s[o];
    }
    float mx = lg[0];
#pragma unroll
    for (int o = 1; o < 6; o++) mx = fmaxf(mx, lg[o]);
    float ev[6], sum = 0.f;
#pragma unroll
    for (int o = 0; o < 6; o++) { ev[o] = __expf(lg[o] - mx); sum += ev[o]; }
    float inv = 1.f / sum;
    if (q == 0 && node < NN) {
#pragma unroll
        for (int o = 0; o < 6; o++) out[node * 6 + o] = ev[o] * inv;
    }
}

// ---------------- launch ----------------
extern "C" void kernel_launch(void* const* d_in, const int* in_sizes, int n_in,
                              void* d_out, int out_size) {
    const float* x      = (const float*)d_in[0];
    const int* ei       = (const int*)d_in[1];
    const float* ea     = (const float*)d_in[2];
    const float* Wq     = (const float*)d_in[3];
    const float* bq     = (const float*)d_in[4];
    const float* Wk     = (const float*)d_in[5];
    const float* bk     = (const float*)d_in[6];
    const float* Wv     = (const float*)d_in[7];
    const float* bv     = (const float*)d_in[8];
    const float* We     = (const float*)d_in[9];
    const float* Wskip  = (const float*)d_in[10];
    const float* bskip  = (const float*)d_in[11];
    const float* W1     = (const float*)d_in[12];
    const float* b1     = (const float*)d_in[13];
    const float* W2     = (const float*)d_in[14];
    const float* b2     = (const float*)d_in[15];
    const float* W3     = (const float*)d_in[16];
    const float* b3     = (const float*)d_in[17];
    float* out = (float*)d_out;

    static int attr_set = 0;
    cudaFuncSetAttribute(k6, cudaFuncAttributeMaxDynamicSharedMemorySize, K6DYN);
    (void)attr_set;

    k0a<<<196, 256>>>(Wq, bq, Wk, bk, We);
    k0d<<<904, 256>>>(Wv, bv, We, Wskip, W1, b1, bskip);
    k1<<<391, 256>>>(x);
    k2<<<391, 256>>>(ei, x, ea);
    k6<<<391, 256, K6DYN>>>(x, W2, b2, W3, b3, out);
}

// round 5
// speedup vs baseline: 2.7251x; 1.1569x over previous
#include <cuda_runtime.h>

#define NN 25000
#define EE 100000
#define NH 4
#define CC 280
#define HC 1120

// ---------------- scratch ----------------
__device__ __align__(16) float g_M[NH * 256];
__device__ __align__(16) float g_G[NH * 6 * 16];
__device__ __align__(16) float g_g0[NH * 6];
__device__ __align__(16) float g_u[NH * 16];
__device__ __align__(16) float g_w[NH * 16];
__device__ __align__(16) float g_c0[NH];

__device__ __align__(16) float g_p[NN * 64];     // x_i @ M_h  [N][H][16]
__device__ __align__(16) float g_xgp[NN * 32];   // [N][H][8] (6 used)
__device__ __align__(16) float g_sd[NN * 4];
__device__ __align__(16) float g_ss[NN * 4];

__device__ __align__(16) float g_T[NN * 64];     // sum ex*x[src]  [N][H][16]
__device__ __align__(16) float g_Sp[NN * 32];    // sum ex*ea      [N][H][8] (6 used)
__device__ __align__(16) float g_A[NN * 4];      // sum ex

__device__ __align__(16) float g_Wc[112 * 64];   // combined (W108 @ W1)
__device__ __align__(16) float g_bc[64];         // b1 + bskip @ W1

__device__ __forceinline__ float wsum(float s) {
    s += __shfl_xor_sync(0xffffffffu, s, 16);
    s += __shfl_xor_sync(0xffffffffu, s, 8);
    s += __shfl_xor_sync(0xffffffffu, s, 4);
    s += __shfl_xor_sync(0xffffffffu, s, 2);
    s += __shfl_xor_sync(0xffffffffu, s, 1);
    return s;
}

__device__ __forceinline__ void red4(float* p, float a, float b, float c, float d) {
    asm volatile("red.global.add.v4.f32 [%0], {%1,%2,%3,%4};"
                 :: "l"(__cvta_generic_to_global(p)), "f"(a), "f"(b), "f"(c), "f"(d) : "memory");
}
__device__ __forceinline__ void red2(float* p, float a, float b) {
    asm volatile("red.global.add.v2.f32 [%0], {%1,%2};"
                 :: "l"(__cvta_generic_to_global(p)), "f"(a), "f"(b) : "memory");
}
__device__ __forceinline__ void red1(float* p, float a) {
    asm volatile("red.global.add.f32 [%0], %1;"
                 :: "l"(__cvta_generic_to_global(p)), "f"(a) : "memory");
}

// ---------------- kA: fused k0a (tiny contractions) + k0d (combined MLP weight) ----
// blocks [0,196): warp-per-output contractions (1564 outputs)
// blocks [196,226): thread-per-output Wc/bc (7232 outputs), W1 rows coalesced
__global__ __launch_bounds__(256) void kA(const float* __restrict__ Wq, const float* __restrict__ bq,
                                          const float* __restrict__ Wk, const float* __restrict__ bk,
                                          const float* __restrict__ We, const float* __restrict__ Wv,
                                          const float* __restrict__ bv, const float* __restrict__ Wskip,
                                          const float* __restrict__ W1, const float* __restrict__ b1,
                                          const float* __restrict__ bskip) {
    if (blockIdx.x < 196) {
        int g = blockIdx.x * 8 + (threadIdx.x >> 5);
        int lane = threadIdx.x & 31;
        if (g >= 1564) return;
        const float *pa, *pb;
        float* op;
        if (g < 1024) {
            int h = g >> 8, a = (g >> 4) & 15, b = g & 15;
            pa = Wq + a * HC + h * CC; pb = Wk + b * HC + h * CC; op = &g_M[g];
        } else if (g < 1408) {
            int t = g - 1024, h = t / 96, r = t % 96, dd = r >> 4, a = r & 15;
            pa = Wq + a * HC + h * CC; pb = We + dd * HC + h * CC; op = &g_G[(h * 6 + dd) * 16 + a];
        } else if (g < 1472) {
            int t = g - 1408, h = t >> 4, a = t & 15;
            pa = Wq + a * HC + h * CC; pb = bk + h * CC; op = &g_u[t];
        } else if (g < 1536) {
            int t = g - 1472, h = t >> 4, a = t & 15;
            pa = Wk + a * HC + h * CC; pb = bq + h * CC; op = &g_w[t];
        } else if (g < 1540) {
            int h = g - 1536;
            pa = bq + h * CC; pb = bk + h * CC; op = &g_c0[h];
        } else {
            int t = g - 1540, h = t / 6, dd = t - h * 6;
            pa = bq + h * CC; pb = We + dd * HC + h * CC; op = &g_g0[t];
        }
        float s = 0.f;
        for (int c = lane; c < CC; c += 32) s += pa[c] * pb[c];
        s = wsum(s);
        if (lane == 0) *op = s;
    } else {
        int idx = (blockIdx.x - 196) * 256 + threadIdx.x;
        if (idx < 7168) {
            int j = idx >> 6, c = idx & 63;
            float s = 0.f;
            if (j < 108) {
                const float* src;
                float sc = 0.25f;
                if (j < 64)      { int h = j >> 4, a = j & 15; src = Wv + a * HC + h * CC; }
                else if (j < 88) { int t = j - 64, h = t / 6, dd = t - h * 6; src = We + dd * HC + h * CC; }
                else if (j < 104){ src = Wskip + (j - 88) * CC; sc = 1.f; }
                else             { int h = j - 104; src = bv + h * CC; }
                float s0 = 0.f, s1 = 0.f, s2 = 0.f, s3 = 0.f;
                int k = 0;
                for (; k + 4 <= CC; k += 4) {
                    s0 += src[k]     * W1[(k)     * 64 + c];
                    s1 += src[k + 1] * W1[(k + 1) * 64 + c];
                    s2 += src[k + 2] * W1[(k + 2) * 64 + c];
                    s3 += src[k + 3] * W1[(k + 3) * 64 + c];
                }
                s = ((s0 + s1) + (s2 + s3)) * sc;
            }
            g_Wc[idx] = s;
        } else if (idx < 7232) {
            int c = idx - 7168;
            float s0 = 0.f, s1 = 0.f;
            for (int k = 0; k + 2 <= CC; k += 2) {
                s0 += bskip[k]     * W1[(k)     * 64 + c];
                s1 += bskip[k + 1] * W1[(k + 1) * 64 + c];
            }
            g_bc[c] = s0 + s1 + b1[c];
        }
    }
}

// ---------------- K1: per-(node,head) precompute + zero accumulators ----------------
__global__ __launch_bounds__(256) void k1(const float* __restrict__ x) {
    __shared__ float sM[NH * 256];
    __shared__ float sG[NH * 96];
    __shared__ float sU[NH * 16];
    __shared__ float sW[NH * 16];
    __shared__ float sC0[NH];
    __shared__ float sG0[NH * 6];
    for (int t = threadIdx.x; t < NH * 256; t += 256) sM[t] = g_M[t];
    if (threadIdx.x < NH * 96) sG[threadIdx.x] = g_G[threadIdx.x];
    if (threadIdx.x < NH * 16) { sU[threadIdx.x] = g_u[threadIdx.x]; sW[threadIdx.x] = g_w[threadIdx.x]; }
    if (threadIdx.x < NH) sC0[threadIdx.x] = g_c0[threadIdx.x];
    if (threadIdx.x < NH * 6) sG0[threadIdx.x] = g_g0[threadIdx.x];
    __syncthreads();

    int gid = blockIdx.x * 256 + threadIdx.x;
    int i = gid >> 2, h = gid & 3;
    if (i >= NN) return;
    float xv[16];
    const float4* xr = (const float4*)(x + (size_t)i * 16);
#pragma unroll
    for (int t = 0; t < 4; t++) {
        float4 f = xr[t];
        xv[4 * t + 0] = f.x; xv[4 * t + 1] = f.y; xv[4 * t + 2] = f.z; xv[4 * t + 3] = f.w;
    }
    const float4 z4 = make_float4(0.f, 0.f, 0.f, 0.f);
    float4* po = (float4*)(g_p + i * 64 + h * 16);
    float4* to = (float4*)(g_T + i * 64 + h * 16);
#pragma unroll
    for (int t = 0; t < 4; t++) {
        float pv[4];
#pragma unroll
        for (int j = 0; j < 4; j++) {
            int b = t * 4 + j;
            float s = 0.f;
#pragma unroll
            for (int a = 0; a < 16; a++) s += xv[a] * sM[(h * 16 + a) * 16 + b];
            pv[j] = s;
        }
        po[t] = make_float4(pv[0], pv[1], pv[2], pv[3]);
        to[t] = z4;
    }
    float xg[6];
#pragma unroll
    for (int dd = 0; dd < 6; dd++) {
        float s = sG0[h * 6 + dd];
#pragma unroll
        for (int a = 0; a < 16; a++) s += xv[a] * sG[(h * 6 + dd) * 16 + a];
        xg[dd] = s;
    }
    float4* xo = (float4*)(g_xgp + i * 32 + h * 8);
    xo[0] = make_float4(xg[0], xg[1], xg[2], xg[3]);
    *(float2*)(g_xgp + i * 32 + h * 8 + 4) = make_float2(xg[4], xg[5]);
    float4* so = (float4*)(g_Sp + i * 32 + h * 8);
    so[0] = z4; so[1] = z4;

    float su = sC0[h], sw = 0.f;
#pragma unroll
    for (int a = 0; a < 16; a++) {
        su += xv[a] * sU[h * 16 + a];
        sw += xv[a] * sW[h * 16 + a];
    }
    g_sd[i * 4 + h] = su;
    g_ss[i * 4 + h] = sw;
    g_A[i * 4 + h] = 0.f;
}

// ---------------- K2: edge pass, one thread per (edge, head) ----------------
__global__ __launch_bounds__(256) void k2(const int* __restrict__ ei,
                                          const float* __restrict__ x,
                                          const float* __restrict__ ea) {
    int gid = blockIdx.x * 256 + threadIdx.x;
    if (gid >= EE * 4) return;
    int e = gid >> 2, h = gid & 3;
    int s = __ldg(ei + e);
    int d = __ldg(ei + EE + e);

    float xs[16];
    const float4* xr = (const float4*)(x + (size_t)s * 16);
#pragma unroll
    for (int t = 0; t < 4; t++) {
        float4 f = __ldg(xr + t);
        xs[4 * t + 0] = f.x; xs[4 * t + 1] = f.y; xs[4 * t + 2] = f.z; xs[4 * t + 3] = f.w;
    }
    float eav[6];
    const float2* er = (const float2*)(ea + (size_t)e * 6);
#pragma unroll
    for (int t = 0; t < 3; t++) {
        float2 f = __ldg(er + t);
        eav[2 * t] = f.x; eav[2 * t + 1] = f.y;
    }

    float al = __ldg(g_sd + d * 4 + h) + __ldg(g_ss + s * 4 + h);
    const float4* pd = (const float4*)(g_p + d * 64 + h * 16);
#pragma unroll
    for (int t = 0; t < 4; t++) {
        float4 f = __ldg(pd + t);
        al += f.x * xs[4 * t + 0] + f.y * xs[4 * t + 1] + f.z * xs[4 * t + 2] + f.w * xs[4 * t + 3];
    }
    float4 xga = __ldg((const float4*)(g_xgp + d * 32 + h * 8));
    float2 xgb = __ldg((const float2*)(g_xgp + d * 32 + h * 8 + 4));
    al += eav[0] * xga.x + eav[1] * xga.y + eav[2] * xga.z + eav[3] * xga.w
        + eav[4] * xgb.x + eav[5] * xgb.y;
    al *= 0.05976143046671968f;  // 1/sqrt(280)
    float ex = __expf(al);

    float* Sd = g_Sp + d * 32 + h * 8;
    red4(Sd, ex * eav[0], ex * eav[1], ex * eav[2], ex * eav[3]);
    red2(Sd + 4, ex * eav[4], ex * eav[5]);
    float* Td = g_T + d * 64 + h * 16;
#pragma unroll
    for (int t = 0; t < 4; t++)
        red4(Td + 4 * t, ex * xs[4 * t], ex * xs[4 * t + 1], ex * xs[4 * t + 2], ex * xs[4 * t + 3]);
    red1(g_A + d * 4 + h, ex);
}

// ---------------- K6: fused normalize + F@Wc + relu + W2 + relu + W3 + softmax ----------------
#define FPITCH 68
#define K6DYN ((7168 + 112 * FPITCH) * 4)
__global__ __launch_bounds__(256) void k6(const float* __restrict__ x,
                                          const float* __restrict__ W2,
                                          const float* __restrict__ b2,
                                          const float* __restrict__ W3,
                                          const float* __restrict__ b3,
                                          float* __restrict__ out) {
    extern __shared__ float dyn[];
    float* Wcs = dyn;              // [112][64]
    float* Fs = dyn + 7168;        // [112][FPITCH]
    float* Hs1 = dyn;              // alias of Wcs, [64][68]
    __shared__ float invAs[256], als[256];
    __shared__ float W2s[1024], b2s[16], W3s[96], b3s[6], bcs[64];

    int tid = threadIdx.x;
    int nodeBase = blockIdx.x * 64;

    for (int t = tid; t < 7168; t += 256) Wcs[t] = g_Wc[t];
    for (int t = tid; t < 1024; t += 256) W2s[t] = W2[t];
    if (tid < 16) b2s[tid] = b2[tid];
    if (tid < 96) W3s[tid] = W3[tid];
    if (tid < 6) b3s[tid] = b3[tid];
    if (tid < 64) bcs[tid] = g_bc[tid];
    {
        int n = tid >> 2;
        int node = nodeBase + n;
        float a = (node < NN) ? g_A[node * 4 + (tid & 3)] : 0.f;
        float inv = 1.f / (a + 1e-16f);
        invAs[tid] = inv;
        als[tid] = a * inv;
    }
    __syncthreads();

    // fill Fs[k][n] (pitch 68)
    for (int idx = tid; idx < 1024; idx += 256) {          // T: 64 nodes x 16 vec4
        int n = idx >> 4, v = idx & 15;
        int node = nodeBase + n;
        float4 t4 = (node < NN) ? ((const float4*)g_T)[node * 16 + v]
                                : make_float4(0.f, 0.f, 0.f, 0.f);
        float inv = invAs[n * 4 + (v >> 2)];
        Fs[(v * 4 + 0) * FPITCH + n] = t4.x * inv;
        Fs[(v * 4 + 1) * FPITCH + n] = t4.y * inv;
        Fs[(v * 4 + 2) * FPITCH + n] = t4.z * inv;
        Fs[(v * 4 + 3) * FPITCH + n] = t4.w * inv;
    }
    for (int idx = tid; idx < 2048; idx += 256) {          // S: 64 nodes x (24 used of 32)
        int n = idx >> 5, r = idx & 31;
        if (r < 24) {
            int node = nodeBase + n;
            int h = r / 6, dd = r - h * 6;
            float v = (node < NN) ? g_Sp[node * 32 + h * 8 + dd] * invAs[n * 4 + h] : 0.f;
            Fs[(64 + r) * FPITCH + n] = v;
        }
    }
    for (int idx = tid; idx < 1024; idx += 256) {          // x: 64 nodes x 16
        int n = idx >> 4, f = idx & 15;
        int node = nodeBase + n;
        Fs[(88 + f) * FPITCH + n] = (node < NN) ? x[(size_t)node * 16 + f] : 0.f;
    }
    {
        int n = tid >> 2, h = tid & 3;
        Fs[(104 + h) * FPITCH + n] = als[tid];
        Fs[(108 + h) * FPITCH + n] = 0.f;
    }
    __syncthreads();

    // stage 1: [64 nodes] x [64 cols], K=112, float4 operands
    int tx = tid & 15, ty = tid >> 4;
    float acc[4][4];
#pragma unroll
    for (int i = 0; i < 4; i++)
#pragma unroll
        for (int j = 0; j < 4; j++) acc[i][j] = 0.f;
    const float4* FsV = (const float4*)Fs;
    const float4* WcV = (const float4*)Wcs;
#pragma unroll 4
    for (int k = 0; k < 112; k++) {
        float4 fv = FsV[k * (FPITCH / 4) + ty];
        float4 wv = WcV[k * 16 + tx];
        acc[0][0] += fv.x * wv.x; acc[0][1] += fv.x * wv.y; acc[0][2] += fv.x * wv.z; acc[0][3] += fv.x * wv.w;
        acc[1][0] += fv.y * wv.x; acc[1][1] += fv.y * wv.y; acc[1][2] += fv.y * wv.z; acc[1][3] += fv.y * wv.w;
        acc[2][0] += fv.z * wv.x; acc[2][1] += fv.z * wv.y; acc[2][2] += fv.z * wv.z; acc[2][3] += fv.z * wv.w;
        acc[3][0] += fv.w * wv.x; acc[3][1] += fv.w * wv.y; acc[3][2] += fv.w * wv.z; acc[3][3] += fv.w * wv.w;
    }
    __syncthreads();  // done reading Wcs; safe to alias as Hs1
#pragma unroll
    for (int i = 0; i < 4; i++)
#pragma unroll
        for (int j = 0; j < 4; j++)
            Hs1[(ty * 4 + i) * 68 + tx * 4 + j] = fmaxf(acc[i][j] + bcs[tx * 4 + j], 0.f);
    __syncthreads();

    // stage 2+3: 4 lanes per node
    int n = tid >> 2, q = tid & 3;
    int node = nodeBase + n;
    float h2[4];
#pragma unroll
    for (int mm = 0; mm < 4; mm++) h2[mm] = b2s[q * 4 + mm];
    for (int k = 0; k < 64; k++) {
        float hv = Hs1[n * 68 + k];
#pragma unroll
        for (int mm = 0; mm < 4; mm++) h2[mm] += hv * W2s[k * 16 + q * 4 + mm];
    }
#pragma unroll
    for (int mm = 0; mm < 4; mm++) h2[mm] = fmaxf(h2[mm], 0.f);

    float lg[6];
#pragma unroll
    for (int o = 0; o < 6; o++) {
        float pz = 0.f;
#pragma unroll
        for (int mm = 0; mm < 4; mm++) pz += h2[mm] * W3s[(q * 4 + mm) * 6 + o];
        lg[o] = pz;
    }
#pragma unroll
    for (int o = 0; o < 6; o++) {
        lg[o] += __shfl_xor_sync(0xffffffffu, lg[o], 1);
        lg[o] += __shfl_xor_sync(0xffffffffu, lg[o], 2);
        lg[o] += b3s[o];
    }
    float mx = lg[0];
#pragma unroll
    for (int o = 1; o < 6; o++) mx = fmaxf(mx, lg[o]);
    float ev[6], sum = 0.f;
#pragma unroll
    for (int o = 0; o < 6; o++) { ev[o] = __expf(lg[o] - mx); sum += ev[o]; }
    float inv = 1.f / sum;
    if (q == 0 && node < NN) {
#pragma unroll
        for (int o = 0; o < 6; o++) out[node * 6 + o] = ev[o] * inv;
    }
}

// ---------------- launch ----------------
extern "C" void kernel_launch(void* const* d_in, const int* in_sizes, int n_in,
                              void* d_out, int out_size) {
    const float* x      = (const float*)d_in[0];
    const int* ei       = (const int*)d_in[1];
    const float* ea     = (const float*)d_in[2];
    const float* Wq     = (const float*)d_in[3];
    const float* bq     = (const float*)d_in[4];
    const float* Wk     = (const float*)d_in[5];
    const float* bk     = (const float*)d_in[6];
    const float* Wv     = (const float*)d_in[7];
    const float* bv     = (const float*)d_in[8];
    const float* We     = (const float*)d_in[9];
    const float* Wskip  = (const float*)d_in[10];
    const float* bskip  = (const float*)d_in[11];
    const float* W1     = (const float*)d_in[12];
    const float* b1     = (const float*)d_in[13];
    const float* W2     = (const float*)d_in[14];
    const float* b2     = (const float*)d_in[15];
    const float* W3     = (const float*)d_in[16];
    const float* b3     = (const float*)d_in[17];
    float* out = (float*)d_out;

    cudaFuncSetAttribute(k6, cudaFuncAttributeMaxDynamicSharedMemorySize, K6DYN);

    kA<<<226, 256>>>(Wq, bq, Wk, bk, We, Wv, bv, Wskip, W1, b1, bskip);
    k1<<<391, 256>>>(x);
    k2<<<1563, 256>>>(ei, x, ea);
    k6<<<391, 256, K6DYN>>>(x, W2, b2, W3, b3, out);
}